// round 2
// baseline (speedup 1.0000x reference)
#include <cuda_runtime.h>
#include <cuda_bf16.h>
#include <cstdint>

// Problem constants (hardcoded per reference)
#define T_STEPS 2048
#define R_DIM   1024
#define B_DIM   8
#define H_DIM   256
#define I_DIM   128

#define NCTA 128      // persistent grid: <= 148 SMs -> all resident
#define NTHR 256      // 8 warps

// ---------------------------------------------------------------------------
// Device-global scratch (allocation-free rule: __device__ arrays)
// ---------------------------------------------------------------------------
__device__ float    g_uin[(size_t)T_STEPS * R_DIM * B_DIM];  // uin[t][r][b], 64MB
__device__ float    g_x[2][B_DIM * R_DIM];                   // reservoir state ping-pong
__device__ float    g_p[2][B_DIM * H_DIM];                   // pca state ping-pong
__device__ float    g_h[2][B_DIM * H_DIM];                   // gate hidden ping-pong
__device__ unsigned g_bar;                                   // grid barrier counter

// ---------------------------------------------------------------------------
// Packed butterfly reduction: reduce N per-thread values across 32 lanes.
// N=64 -> each lane ends with 2 sums, value v = 2*lane + slot.
// N=16 -> lanes l, l^1 end with the same sum, v = (lane>>1)&15.
// ---------------------------------------------------------------------------
template <int N>
__device__ __forceinline__ void butterfly_reduce(float* acc, unsigned lane) {
    int n = N;
#pragma unroll
    for (int off = 16; off >= 1; off >>= 1) {
        if (n > 1) {
            const int h = n >> 1;
            const bool up = (lane & off) != 0;
#pragma unroll
            for (int i = 0; i < h; ++i) {
                float send = up ? acc[i] : acc[i + h];
                float recv = __shfl_xor_sync(0xffffffffu, send, off);
                if (up) acc[i + h] += recv; else acc[i] += recv;
            }
            if (up) {
#pragma unroll
                for (int i = 0; i < h; ++i) acc[i] = acc[i + h];
            }
            n = h;
        } else {
            acc[0] += __shfl_xor_sync(0xffffffffu, acc[0], off);
        }
    }
}

// ---------------------------------------------------------------------------
// Grid barrier: monotonic counter, release(fence)+arrive / spin+acquire.
// Cross-CTA data uses .cg (L2-only) accesses, so post-barrier loads are fresh.
// ---------------------------------------------------------------------------
__device__ __forceinline__ void grid_barrier(int iter, int tid) {
    __syncthreads();
    if (tid == 0) {
        __threadfence();
        atomicAdd(&g_bar, 1u);
        const unsigned target = (unsigned)(iter + 1) * NCTA;
        while (atomicAdd(&g_bar, 0u) < target) { }
        __threadfence();
    }
    __syncthreads();
}

// ---------------------------------------------------------------------------
// Kernel A: uin[t][r][b] = sum_i u[b][t][i] * w_in[r][i] + w_bias[r]
// grid (4, 32): block = 256 r-rows x 64 timesteps. W tile staged once per block.
// ---------------------------------------------------------------------------
#define UIN_WPAD 132  // 128 + 4 pad: conflict-free float4 LDS, 16B aligned
#define UIN_SMEM (256 * UIN_WPAD * 4 + B_DIM * I_DIM * 4)

__global__ void __launch_bounds__(256) uin_kernel(
    const float* __restrict__ u, const float* __restrict__ w_in,
    const float* __restrict__ w_bias)
{
    extern __shared__ float sm[];
    float* w_s = sm;                         // [256][UIN_WPAD]
    float* u_s = sm + 256 * UIN_WPAD;        // [8][128]

    const int tid = threadIdx.x;
    const int r0  = blockIdx.x * 256;
    const int t0  = blockIdx.y * 64;

    for (int j = tid; j < 256 * I_DIM; j += 256) {
        int row = j >> 7, i = j & 127;
        w_s[row * UIN_WPAD + i] = w_in[(r0 + row) * I_DIM + i];
    }
    const float bias = w_bias[r0 + tid];

    for (int tt = 0; tt < 64; ++tt) {
        const int t = t0 + tt;
        __syncthreads();
        for (int j = tid; j < B_DIM * I_DIM; j += 256) {
            int b = j >> 7, i = j & 127;
            u_s[j] = u[((size_t)b * T_STEPS + t) * I_DIM + i];
        }
        __syncthreads();

        float acc[B_DIM];
#pragma unroll
        for (int b = 0; b < B_DIM; ++b) acc[b] = bias;

        const float4* wrow = reinterpret_cast<const float4*>(&w_s[tid * UIN_WPAD]);
#pragma unroll 8
        for (int i4 = 0; i4 < I_DIM / 4; ++i4) {
            float4 w4 = wrow[i4];
#pragma unroll
            for (int b = 0; b < B_DIM; ++b) {
                float4 u4 = reinterpret_cast<const float4*>(&u_s[b * I_DIM])[i4];
                acc[b] = fmaf(w4.x, u4.x, acc[b]);
                acc[b] = fmaf(w4.y, u4.y, acc[b]);
                acc[b] = fmaf(w4.z, u4.z, acc[b]);
                acc[b] = fmaf(w4.w, u4.w, acc[b]);
            }
        }
        float* dst = &g_uin[((size_t)t * R_DIM + r0 + tid) * B_DIM];
        float4 o0 = make_float4(acc[0], acc[1], acc[2], acc[3]);
        float4 o1 = make_float4(acc[4], acc[5], acc[6], acc[7]);
        reinterpret_cast<float4*>(dst)[0] = o0;
        reinterpret_cast<float4*>(dst)[1] = o1;
    }
}

// ---------------------------------------------------------------------------
// Kernel B: persistent fused recurrence.
// Iteration k: reservoir computes x_k (k<T), pca computes p_{k-1} (1<=k<=T),
// gate computes h_{k-2} (k>=2). One grid barrier per iteration.
// CTA c owns W rows [8c,8c+8), W_pca cols {2c,2c+1}, gate rows {2c,2c+1}.
// ---------------------------------------------------------------------------
__global__ void __launch_bounds__(NTHR, 1) esn_persistent(
    const float* __restrict__ w,      // (R,R)
    const float* __restrict__ w_pca,  // (R,H)
    const float* __restrict__ wzp,    // (H,H)
    const float* __restrict__ wzh,    // (H,H)
    const float* __restrict__ bz,     // (H)
    float* __restrict__ out)          // (B,T,H)
{
    __shared__ float w_s[8 * R_DIM];     // 32 KB
    __shared__ float wp_s[2 * R_DIM];    // 8 KB
    __shared__ float wzp_s[2 * H_DIM];   // 2 KB
    __shared__ float wzh_s[2 * H_DIM];   // 2 KB
    __shared__ float bz_s[2];
    __shared__ float red[NTHR * 2];      // 2 KB reduction scratch

    const int tid  = threadIdx.x;
    const int cta  = blockIdx.x;
    const int warp = tid >> 5;
    const unsigned lane = tid & 31;

    // One-time weight staging
    for (int j = tid; j < 8 * R_DIM; j += NTHR)
        w_s[j] = w[(size_t)cta * 8 * R_DIM + j];
    for (int j = tid; j < 2 * R_DIM; j += NTHR) {
        int hh = j >> 10, r = j & (R_DIM - 1);
        wp_s[j] = w_pca[(size_t)r * H_DIM + cta * 2 + hh];
    }
    for (int j = tid; j < 2 * H_DIM; j += NTHR) {
        int hi = j >> 8, hq = j & (H_DIM - 1);
        wzp_s[j] = wzp[(cta * 2 + hi) * H_DIM + hq];
        wzh_s[j] = wzh[(cta * 2 + hi) * H_DIM + hq];
    }
    if (tid < 2) bz_s[tid] = bz[cta * 2 + tid];
    __syncthreads();

    for (int k = 0; k <= T_STEPS + 1; ++k) {
        if (k <= T_STEPS) {
            const bool do_res = (k < T_STEPS);
            const bool do_pca = (k >= 1);

            float racc[64];
            float pacc[16];
#pragma unroll
            for (int i = 0; i < 64; ++i) racc[i] = 0.f;
#pragma unroll
            for (int i = 0; i < 16; ++i) pacc[i] = 0.f;

            if (k >= 1) {
                const float* xo = g_x[(k + 1) & 1];   // x_{k-1}
#pragma unroll
                for (int c = 0; c < 4; ++c) {
                    const int r = warp * 128 + c * 32 + (int)lane;
                    float xv[B_DIM];
#pragma unroll
                    for (int b = 0; b < B_DIM; ++b)
                        xv[b] = __ldcg(&xo[b * R_DIM + r]);
                    if (do_res) {
#pragma unroll
                        for (int row = 0; row < 8; ++row) {
                            const float wv = w_s[row * R_DIM + r];
#pragma unroll
                            for (int b = 0; b < B_DIM; ++b)
                                racc[row * 8 + b] = fmaf(wv, xv[b], racc[row * 8 + b]);
                        }
                    }
#pragma unroll
                    for (int hh = 0; hh < 2; ++hh) {
                        const float wv = wp_s[hh * R_DIM + r];
#pragma unroll
                        for (int b = 0; b < B_DIM; ++b)
                            pacc[hh * 8 + b] = fmaf(wv, xv[b], pacc[hh * 8 + b]);
                    }
                }
            }

            if (do_res) {
                butterfly_reduce<64>(racc, lane);
                red[warp * 64 + 2 * lane + 0] = racc[0];
                red[warp * 64 + 2 * lane + 1] = racc[1];
                __syncthreads();
                if (tid < 64) {
                    float s = 0.f;
#pragma unroll
                    for (int wj = 0; wj < 8; ++wj) s += red[wj * 64 + tid];
                    const int rg = cta * 8 + (tid >> 3);
                    const int b  = tid & 7;
                    const float val =
                        tanhf(g_uin[((size_t)k * R_DIM + rg) * B_DIM + b] + s);
                    __stcg(&g_x[k & 1][b * R_DIM + rg], val);
                }
                __syncthreads();
            }

            if (do_pca) {
                butterfly_reduce<16>(pacc, lane);
                if ((lane & 1) == 0) red[warp * 16 + (lane >> 1)] = pacc[0];
                __syncthreads();
                if (tid < 16) {
                    float s = 0.f;
#pragma unroll
                    for (int wj = 0; wj < 8; ++wj) s += red[wj * 16 + tid];
                    const int h = cta * 2 + (tid >> 3);
                    const int b = tid & 7;
                    __stcg(&g_p[(k - 1) & 1][b * H_DIM + h], s);
                }
                __syncthreads();
            }
        }

        // Gate for t = k-2 (warp = batch, CTA owns 2 h-rows)
        if (k >= 2) {
            const int t = k - 2;
            const float* p  = g_p[t & 1];
            const float* hp = g_h[(t + 1) & 1];  // h_{t-1} (ping-pong)
            const bool have_h = (t > 0);
            const int b = warp;

            float sacc0 = 0.f, sacc1 = 0.f;
#pragma unroll
            for (int c = 0; c < 8; ++c) {
                const int hq = c * 32 + (int)lane;
                const float pv = __ldcg(&p[b * H_DIM + hq]);
                const float hv = have_h ? __ldcg(&hp[b * H_DIM + hq]) : 0.f;
                sacc0 = fmaf(pv, wzp_s[hq],        fmaf(hv, wzh_s[hq],        sacc0));
                sacc1 = fmaf(pv, wzp_s[H_DIM + hq], fmaf(hv, wzh_s[H_DIM + hq], sacc1));
            }
#pragma unroll
            for (int off = 16; off >= 1; off >>= 1) {
                sacc0 += __shfl_xor_sync(0xffffffffu, sacc0, off);
                sacc1 += __shfl_xor_sync(0xffffffffu, sacc1, off);
            }
            if (lane < 2) {
                const int h = cta * 2 + (int)lane;
                const float s = (lane == 0 ? sacc0 : sacc1) + bz_s[lane];
                const float z = 1.f / (1.f + expf(-s));
                const float hv = have_h ? __ldcg(&hp[b * H_DIM + h]) : 0.f;
                const float pv = __ldcg(&p[b * H_DIM + h]);
                const float hn = (1.f - z) * hv + z * pv;
                __stcg(&g_h[t & 1][b * H_DIM + h], hn);
                out[((size_t)b * T_STEPS + t) * H_DIM + h] = hn;
            }
        }

        grid_barrier(k, tid);
    }
}

// ---------------------------------------------------------------------------
// Launch
// ---------------------------------------------------------------------------
extern "C" void kernel_launch(void* const* d_in, const int* in_sizes, int n_in,
                              void* d_out, int out_size) {
    const float* u      = (const float*)d_in[0];
    const float* w_in   = (const float*)d_in[1];
    const float* w      = (const float*)d_in[2];
    const float* w_bias = (const float*)d_in[3];
    const float* w_pca  = (const float*)d_in[4];
    const float* wzp    = (const float*)d_in[5];
    const float* wzh    = (const float*)d_in[6];
    const float* bz     = (const float*)d_in[7];
    float* out = (float*)d_out;

    // Reset grid-barrier counter every call (captured into the graph).
    void* bar_addr = nullptr;
    cudaGetSymbolAddress(&bar_addr, g_bar);
    cudaMemsetAsync(bar_addr, 0, sizeof(unsigned));

    cudaFuncSetAttribute(uin_kernel,
                         cudaFuncAttributeMaxDynamicSharedMemorySize, UIN_SMEM);
    uin_kernel<<<dim3(4, 32), 256, UIN_SMEM>>>(u, w_in, w_bias);

    esn_persistent<<<NCTA, NTHR>>>(w, w_pca, wzp, wzh, bz, out);
}

// round 3
// speedup vs baseline: 1.2510x; 1.2510x over previous
#include <cuda_runtime.h>
#include <cuda_bf16.h>
#include <cstdint>

typedef unsigned long long ull;

// Problem constants
#define T_STEPS 2048
#define R_DIM   1024
#define B_DIM   8
#define H_DIM   256
#define I_DIM   128

#define NCTA 128
#define NTHR 256

// ---------------------------------------------------------------------------
// Device-global scratch
// ---------------------------------------------------------------------------
__device__ float    g_uin[(size_t)T_STEPS * R_DIM * B_DIM];  // [t][r][b]
__device__ float    g_x[2][R_DIM * B_DIM];                   // [buf][r*8+b]  (b contiguous!)
__device__ float    g_p[2][B_DIM * H_DIM];                   // [buf][b*H+h]
__device__ float    g_h[2][B_DIM * H_DIM];                   // [buf][b*H+h]
__device__ unsigned g_bar;

// ---------------------------------------------------------------------------
// Packed f32x2 helpers (Blackwell FFMA2 path — PTX only)
// ---------------------------------------------------------------------------
__device__ __forceinline__ ull f32x2_fma(ull a, ull b, ull c) {
    ull d;
    asm("fma.rn.f32x2 %0, %1, %2, %3;" : "=l"(d) : "l"(a), "l"(b), "l"(c));
    return d;
}
__device__ __forceinline__ ull f32x2_add(ull a, ull b) {
    ull d;
    asm("add.rn.f32x2 %0, %1, %2;" : "=l"(d) : "l"(a), "l"(b));
    return d;
}
__device__ __forceinline__ void ldcg_v2u64(const ull* p, ull& a, ull& b) {
    asm volatile("ld.global.cg.v2.u64 {%0,%1}, [%2];" : "=l"(a), "=l"(b) : "l"(p));
}
__device__ __forceinline__ ull pack_dup(float w) {
    unsigned u = __float_as_uint(w);
    return ((ull)u << 32) | (ull)u;
}

// ---------------------------------------------------------------------------
// Packed butterfly reduction on f32x2 values.
// N=32 -> lane l ends with value v=l in acc[0].
// N=8  -> lane l ends with value v=(l>>2)&7, duplicated across (l&3).
// ---------------------------------------------------------------------------
template <int N>
__device__ __forceinline__ void butterfly_reduce2(ull* acc, unsigned lane) {
    int n = N;
#pragma unroll
    for (int off = 16; off >= 1; off >>= 1) {
        if (n > 1) {
            const int h = n >> 1;
            const bool up = (lane & off) != 0;
#pragma unroll
            for (int i = 0; i < h; ++i) {
                ull send = up ? acc[i] : acc[i + h];
                ull recv = __shfl_xor_sync(0xffffffffu, send, off);
                if (up) acc[i + h] = f32x2_add(acc[i + h], recv);
                else    acc[i]     = f32x2_add(acc[i], recv);
            }
            if (up) {
#pragma unroll
                for (int i = 0; i < h; ++i) acc[i] = acc[i + h];
            }
            n = h;
        } else {
            acc[0] = f32x2_add(acc[0], __shfl_xor_sync(0xffffffffu, acc[0], off));
        }
    }
}

// ---------------------------------------------------------------------------
// Kernel A: uin[t][r][b] = u[b][t][:] . w_in[r][:] + w_bias[r]   (unchanged)
// ---------------------------------------------------------------------------
#define UIN_WPAD 132
#define UIN_SMEM (256 * UIN_WPAD * 4 + B_DIM * I_DIM * 4)

__global__ void __launch_bounds__(256) uin_kernel(
    const float* __restrict__ u, const float* __restrict__ w_in,
    const float* __restrict__ w_bias)
{
    extern __shared__ float sm[];
    float* w_s = sm;
    float* u_s = sm + 256 * UIN_WPAD;

    const int tid = threadIdx.x;
    const int r0  = blockIdx.x * 256;
    const int t0  = blockIdx.y * 64;

    for (int j = tid; j < 256 * I_DIM; j += 256) {
        int row = j >> 7, i = j & 127;
        w_s[row * UIN_WPAD + i] = w_in[(r0 + row) * I_DIM + i];
    }
    const float bias = w_bias[r0 + tid];

    for (int tt = 0; tt < 64; ++tt) {
        const int t = t0 + tt;
        __syncthreads();
        for (int j = tid; j < B_DIM * I_DIM; j += 256) {
            int b = j >> 7, i = j & 127;
            u_s[j] = u[((size_t)b * T_STEPS + t) * I_DIM + i];
        }
        __syncthreads();

        float acc[B_DIM];
#pragma unroll
        for (int b = 0; b < B_DIM; ++b) acc[b] = bias;

        const float4* wrow = reinterpret_cast<const float4*>(&w_s[tid * UIN_WPAD]);
#pragma unroll 8
        for (int i4 = 0; i4 < I_DIM / 4; ++i4) {
            float4 w4 = wrow[i4];
#pragma unroll
            for (int b = 0; b < B_DIM; ++b) {
                float4 u4 = reinterpret_cast<const float4*>(&u_s[b * I_DIM])[i4];
                acc[b] = fmaf(w4.x, u4.x, acc[b]);
                acc[b] = fmaf(w4.y, u4.y, acc[b]);
                acc[b] = fmaf(w4.z, u4.z, acc[b]);
                acc[b] = fmaf(w4.w, u4.w, acc[b]);
            }
        }
        float* dst = &g_uin[((size_t)t * R_DIM + r0 + tid) * B_DIM];
        reinterpret_cast<float4*>(dst)[0] = make_float4(acc[0], acc[1], acc[2], acc[3]);
        reinterpret_cast<float4*>(dst)[1] = make_float4(acc[4], acc[5], acc[6], acc[7]);
    }
}

// ---------------------------------------------------------------------------
// Kernel B: persistent fused recurrence with cheap grid barrier.
// SMEM layout (dynamic, ~88.6 KB):
//   w2   : 8*1024 ull  (W rows, each value duplicated {w,w})
//   wp2  : 2*1024 ull  (W_pca cols, duplicated)
//   red2 : 8*32 ull    (res reduction scratch)
//   redp2: 8*8 ull     (pca reduction scratch)
//   wzp_s, wzh_s : 512 floats each; bz_s : 2 floats
// ---------------------------------------------------------------------------
#define SM_W2    0
#define SM_WP2   (8 * 1024)
#define SM_RED   (SM_WP2 + 2 * 1024)
#define SM_REDP  (SM_RED + 256)
#define SM_ULLS  (SM_REDP + 64)
#define ESN_SMEM (SM_ULLS * 8 + (512 + 512 + 2) * 4)

__device__ __forceinline__ void gate_step(
    int t, int cta, int warp, unsigned lane,
    const float* wzp_s, const float* wzh_s, const float* bz_s,
    float* __restrict__ out)
{
    const float* p  = g_p[t & 1];
    const float* hp = g_h[(t + 1) & 1];
    const bool have_h = (t > 0);
    const int b = warp;

    float sacc0 = 0.f, sacc1 = 0.f;
#pragma unroll
    for (int c = 0; c < 8; ++c) {
        const int hq = c * 32 + (int)lane;
        const float pv = __ldcg(&p[b * H_DIM + hq]);
        const float hv = have_h ? __ldcg(&hp[b * H_DIM + hq]) : 0.f;
        sacc0 = fmaf(pv, wzp_s[hq],         fmaf(hv, wzh_s[hq],         sacc0));
        sacc1 = fmaf(pv, wzp_s[H_DIM + hq], fmaf(hv, wzh_s[H_DIM + hq], sacc1));
    }
#pragma unroll
    for (int off = 16; off >= 1; off >>= 1) {
        sacc0 += __shfl_xor_sync(0xffffffffu, sacc0, off);
        sacc1 += __shfl_xor_sync(0xffffffffu, sacc1, off);
    }
    if (lane < 2) {
        const int h = cta * 2 + (int)lane;
        const float s = (lane == 0 ? sacc0 : sacc1) + bz_s[lane];
        const float z = 1.f / (1.f + __expf(-s));
        const float hv = have_h ? __ldcg(&hp[b * H_DIM + h]) : 0.f;
        const float pv = __ldcg(&p[b * H_DIM + h]);
        const float hn = (1.f - z) * hv + z * pv;
        __stcg(&g_h[t & 1][b * H_DIM + h], hn);
        out[((size_t)b * T_STEPS + t) * H_DIM + h] = hn;
    }
}

__global__ void __launch_bounds__(NTHR, 1) esn_persistent(
    const float* __restrict__ w,
    const float* __restrict__ w_pca,
    const float* __restrict__ wzp,
    const float* __restrict__ wzh,
    const float* __restrict__ bz,
    float* __restrict__ out)
{
    extern __shared__ ull smu[];
    ull* w2    = smu + SM_W2;
    ull* wp2   = smu + SM_WP2;
    ull* red2  = smu + SM_RED;
    ull* redp2 = smu + SM_REDP;
    float* wzp_s = (float*)(smu + SM_ULLS);
    float* wzh_s = wzp_s + 512;
    float* bz_s  = wzh_s + 512;
    float* redf  = (float*)red2;
    float* redpf = (float*)redp2;

    const int tid  = threadIdx.x;
    const int cta  = blockIdx.x;
    const int warp = tid >> 5;
    const unsigned lane = tid & 31;

    // One-time weight staging (duplicated pairs for f32x2)
    for (int j = tid; j < 8 * R_DIM; j += NTHR)
        w2[j] = pack_dup(w[(size_t)cta * 8 * R_DIM + j]);
    for (int j = tid; j < 2 * R_DIM; j += NTHR) {
        int hh = j >> 10, r = j & (R_DIM - 1);
        wp2[j] = pack_dup(w_pca[(size_t)r * H_DIM + cta * 2 + hh]);
    }
    for (int j = tid; j < 2 * H_DIM; j += NTHR) {
        int hi = j >> 8, hq = j & (H_DIM - 1);
        wzp_s[j] = wzp[(cta * 2 + hi) * H_DIM + hq];
        wzh_s[j] = wzh[(cta * 2 + hi) * H_DIM + hq];
    }
    if (tid < 2) bz_s[tid] = bz[cta * 2 + tid];
    __syncthreads();

    for (int k = 0; k <= T_STEPS; ++k) {
        const bool do_res = (k < T_STEPS);
        const bool do_pca = (k >= 1);

        // ---- gate for t = k-2 (uses data published by barrier k-1) ----
        if (k >= 2) gate_step(k - 2, cta, warp, lane, wzp_s, wzh_s, bz_s, out);

        // ---- MAC phase: reservoir rows (8) + pca cols (2), batch-packed ----
        ull racc[32];
        ull pacc[8];
#pragma unroll
        for (int i = 0; i < 32; ++i) racc[i] = 0ull;
#pragma unroll
        for (int i = 0; i < 8; ++i) pacc[i] = 0ull;

        if (k >= 1) {
            const ull* xo = (const ull*)g_x[(k + 1) & 1];  // x_{k-1}, [r][4] ull
#pragma unroll
            for (int c = 0; c < 4; ++c) {
                const int r = warp * 128 + c * 32 + (int)lane;
                ull xv[4];
                ldcg_v2u64(xo + (size_t)r * 4,     xv[0], xv[1]);
                ldcg_v2u64(xo + (size_t)r * 4 + 2, xv[2], xv[3]);
                if (do_res) {
#pragma unroll
                    for (int row = 0; row < 8; ++row) {
                        const ull wpp = w2[row * R_DIM + r];
#pragma unroll
                        for (int bp = 0; bp < 4; ++bp)
                            racc[row * 4 + bp] = f32x2_fma(wpp, xv[bp], racc[row * 4 + bp]);
                    }
                }
#pragma unroll
                for (int hh = 0; hh < 2; ++hh) {
                    const ull wpp = wp2[hh * R_DIM + r];
#pragma unroll
                    for (int bp = 0; bp < 4; ++bp)
                        pacc[hh * 4 + bp] = f32x2_fma(wpp, xv[bp], pacc[hh * 4 + bp]);
                }
            }
        }

        // ---- intra-warp reductions + scratch stores ----
        if (do_res) {
            butterfly_reduce2<32>(racc, lane);
            red2[warp * 32 + lane] = racc[0];
        }
        if (do_pca) {
            butterfly_reduce2<8>(pacc, lane);
            if ((lane & 3) == 0) redp2[warp * 8 + (lane >> 2)] = pacc[0];
        }
        __syncthreads();

        // ---- finalize: cross-warp sums, activation, publish state ----
        if (do_res && tid < 64) {
            float s = 0.f;
#pragma unroll
            for (int wj = 0; wj < 8; ++wj) s += redf[wj * 64 + tid];
            const float val = tanhf(g_uin[(size_t)k * 8192 + cta * 64 + tid] + s);
            __stcg(&g_x[k & 1][cta * 64 + tid], val);
        }
        if (do_pca && tid < 16) {
            float s = 0.f;
#pragma unroll
            for (int wj = 0; wj < 8; ++wj) s += redpf[wj * 16 + tid];
            const int h = cta * 2 + (tid >> 3);
            const int b = tid & 7;
            __stcg(&g_p[(k - 1) & 1][b * H_DIM + h], s);
        }
        __syncthreads();   // all stores ordered before arrive; protects scratch WAR

        // ---- grid barrier: red.release arrive + ld.acquire poll ----
        if (tid == 0) {
            asm volatile("red.release.gpu.global.add.u32 [%0], %1;"
                         :: "l"(&g_bar), "r"(1u) : "memory");
            const unsigned target = (unsigned)(k + 1) * NCTA;
            unsigned v;
            do {
                asm volatile("ld.acquire.gpu.global.u32 %0, [%1];"
                             : "=r"(v) : "l"(&g_bar) : "memory");
            } while (v < target);
        }
        __syncthreads();
    }

    // ---- last gate step: t = T-1 (published by barrier at k = T) ----
    gate_step(T_STEPS - 1, cta, warp, lane, wzp_s, wzh_s, bz_s, out);
}

// ---------------------------------------------------------------------------
// Launch
// ---------------------------------------------------------------------------
extern "C" void kernel_launch(void* const* d_in, const int* in_sizes, int n_in,
                              void* d_out, int out_size) {
    const float* u      = (const float*)d_in[0];
    const float* w_in   = (const float*)d_in[1];
    const float* w      = (const float*)d_in[2];
    const float* w_bias = (const float*)d_in[3];
    const float* w_pca  = (const float*)d_in[4];
    const float* wzp    = (const float*)d_in[5];
    const float* wzh    = (const float*)d_in[6];
    const float* bz     = (const float*)d_in[7];
    float* out = (float*)d_out;

    void* bar_addr = nullptr;
    cudaGetSymbolAddress(&bar_addr, g_bar);
    cudaMemsetAsync(bar_addr, 0, sizeof(unsigned));

    cudaFuncSetAttribute(uin_kernel,
                         cudaFuncAttributeMaxDynamicSharedMemorySize, UIN_SMEM);
    uin_kernel<<<dim3(4, 32), 256, UIN_SMEM>>>(u, w_in, w_bias);

    cudaFuncSetAttribute(esn_persistent,
                         cudaFuncAttributeMaxDynamicSharedMemorySize, ESN_SMEM);
    esn_persistent<<<NCTA, NTHR, ESN_SMEM>>>(w, w_pca, wzp, wzh, bz, out);
}